// round 1
// baseline (speedup 1.0000x reference)
#include <cuda_runtime.h>

// Problem constants
#define NB   32      // batch
#define NT_  1024    // target time
#define NL   1023    // decoder length after slice
#define NS   1024    // source length
#define NH   256     // H
#define NC2  512     // 2H
#define NE   256     // E
#define NM1  32768   // NB*NT_
#define NM2  32736   // NB*NL
#define KCONV 1536   // 3*512

// ------------------------- scratch (static device globals) -------------------
__device__ float g_G  [NM1 * NE];      // gathered embeddings          134/4 MB
__device__ float g_u  [NM1 * NC2];     // pre-conv activations (B,T,512)
__device__ float g_col[NM2 * KCONV];   // im2col                         201 MB
__device__ float g_y  [NM2 * NC2];     // conv output
__device__ float g_dec[NM2 * NH];      // dec_attn
__device__ float g_sc [NM2 * NS];      // scores / attn                  134 MB

// ------------------------- gather: G[m] = emb[target[t][b]] ------------------
__global__ void gather_kernel(const int* __restrict__ target,
                              const float* __restrict__ emb) {
    int gid = blockIdx.x * blockDim.x + threadIdx.x;   // over NM1*64 float4
    if (gid >= NM1 * 64) return;
    int m  = gid >> 6;
    int e4 = gid & 63;
    int b = m >> 10, t = m & 1023;
    int idx = target[t * NB + b];
    ((float4*)g_G)[(long)m * 64 + e4] =
        ((const float4*)emb)[(long)idx * 64 + e4];
}

// ------------------------- im2col for K=3 temporal conv ----------------------
__global__ void im2col_kernel() {
    long gid = (long)blockIdx.x * blockDim.x + threadIdx.x; // over NM2*384 f4
    if (gid >= (long)NM2 * 384) return;
    int m = (int)(gid / 384);
    int j = (int)(gid % 384);
    int kh = j >> 7;          // (j*4)/512
    int w4 = j & 127;
    int b = m / NL, l = m % NL;
    int t = l - 2 + kh;
    float4 v = make_float4(0.f, 0.f, 0.f, 0.f);
    if (t >= 0)
        v = ((const float4*)g_u)[((long)(b * NT_ + t)) * 128 + w4];
    ((float4*)g_col)[(long)m * 384 + j] = v;
}

// ------------------------- GLU: relu + channel softmax * gate ----------------
__global__ void glu_kernel() {
    int m = blockIdx.x;        // row (b*NL+l)
    int h = threadIdx.x;       // 0..255
    float a = g_y[(long)m * NC2 + h];
    float g = g_y[(long)m * NC2 + NH + h];
    a = fmaxf(a, 0.f);
    g = fmaxf(g, 0.f);

    __shared__ float red[8];
    float v = g;
    #pragma unroll
    for (int o = 16; o > 0; o >>= 1)
        v = fmaxf(v, __shfl_xor_sync(0xffffffffu, v, o));
    if ((h & 31) == 0) red[h >> 5] = v;
    __syncthreads();
    float mx = red[0];
    #pragma unroll
    for (int i = 1; i < 8; i++) mx = fmaxf(mx, red[i]);

    float e = expf(g - mx);
    __syncthreads();
    v = e;
    #pragma unroll
    for (int o = 16; o > 0; o >>= 1)
        v += __shfl_xor_sync(0xffffffffu, v, o);
    if ((h & 31) == 0) red[h >> 5] = v;
    __syncthreads();
    float sum = 0.f;
    #pragma unroll
    for (int i = 0; i < 8; i++) sum += red[i];

    g_dec[(long)m * NH + h] = a * e / sum;
}

// ------------------------- row softmax over scores (len 1024) ----------------
__global__ void softmax_rows_kernel() {
    int m = blockIdx.x;                       // 0..NM2-1
    int h = threadIdx.x;                      // 0..255
    float* row = g_sc + (long)m * NS;
    float x0 = row[h], x1 = row[h + 256], x2 = row[h + 512], x3 = row[h + 768];

    __shared__ float red[8];
    float v = fmaxf(fmaxf(x0, x1), fmaxf(x2, x3));
    #pragma unroll
    for (int o = 16; o > 0; o >>= 1)
        v = fmaxf(v, __shfl_xor_sync(0xffffffffu, v, o));
    if ((h & 31) == 0) red[h >> 5] = v;
    __syncthreads();
    float mx = red[0];
    #pragma unroll
    for (int i = 1; i < 8; i++) mx = fmaxf(mx, red[i]);

    float e0 = expf(x0 - mx), e1 = expf(x1 - mx),
          e2 = expf(x2 - mx), e3 = expf(x3 - mx);
    __syncthreads();
    v = e0 + e1 + e2 + e3;
    #pragma unroll
    for (int o = 16; o > 0; o >>= 1)
        v += __shfl_xor_sync(0xffffffffu, v, o);
    if ((h & 31) == 0) red[h >> 5] = v;
    __syncthreads();
    float sum = 0.f;
    #pragma unroll
    for (int i = 0; i < 8; i++) sum += red[i];
    float inv = 1.f / sum;

    row[h]       = e0 * inv;
    row[h + 256] = e1 * inv;
    row[h + 512] = e2 * inv;
    row[h + 768] = e3 * inv;
}

// ------------------------- generic tiled SGEMM -------------------------------
// C[M,N] = A[M,K] * (TRANSB ? B[N,K]^T : B[K,N])  (+ bias[n]) (+= existing C)
// Requires: K % 16 == 0, N % 128 == 0. M guarded.
// 128x128 block tile, BK=16, 256 threads, 8x8 per thread.
template <bool TRANSB, bool ACCUM, bool BIAS>
__global__ __launch_bounds__(256, 2)
void sgemm128(const float* __restrict__ A, const float* __restrict__ Bm,
              const float* __restrict__ bias, float* __restrict__ C,
              int M, int N, int K, long sA, long sB, long sC) {
    const int bz = blockIdx.z;
    A  += (long)bz * sA;
    Bm += (long)bz * sB;
    C  += (long)bz * sC;

    __shared__ float As[16][128];
    __shared__ float Bs[16][128];

    const int tid = threadIdx.x;
    const int tx = tid & 15;        // col group
    const int ty = tid >> 4;        // row group
    const int rowBlock = blockIdx.y * 128;
    const int colBlock = blockIdx.x * 128;

    float acc[8][8];
    #pragma unroll
    for (int i = 0; i < 8; i++)
        #pragma unroll
        for (int j = 0; j < 8; j++) acc[i][j] = 0.f;

    const int nK = K >> 4;
    for (int kt = 0; kt < nK; ++kt) {
        const int k0 = kt << 4;
        // load A tile (128 rows x 16 k), transposed into As[k][row]
        #pragma unroll
        for (int i = 0; i < 2; ++i) {
            int slot = tid + i * 256;        // 0..511
            int ar = slot >> 2;              // row in tile
            int ac4 = slot & 3;              // float4 index in k
            int gr = rowBlock + ar;
            float4 v = make_float4(0.f, 0.f, 0.f, 0.f);
            if (gr < M)
                v = *(const float4*)(A + (long)gr * K + k0 + ac4 * 4);
            As[ac4 * 4 + 0][ar] = v.x;
            As[ac4 * 4 + 1][ar] = v.y;
            As[ac4 * 4 + 2][ar] = v.z;
            As[ac4 * 4 + 3][ar] = v.w;
        }
        // load B tile into Bs[k][n]
        if (TRANSB) {
            #pragma unroll
            for (int i = 0; i < 2; ++i) {
                int slot = tid + i * 256;
                int br = slot >> 2;          // n in tile
                int bc4 = slot & 3;          // float4 in k
                float4 v = *(const float4*)(Bm + (long)(colBlock + br) * K + k0 + bc4 * 4);
                Bs[bc4 * 4 + 0][br] = v.x;
                Bs[bc4 * 4 + 1][br] = v.y;
                Bs[bc4 * 4 + 2][br] = v.z;
                Bs[bc4 * 4 + 3][br] = v.w;
            }
        } else {
            #pragma unroll
            for (int i = 0; i < 2; ++i) {
                int slot = tid + i * 256;
                int kr = slot >> 5;          // k row (16)
                int nc4 = slot & 31;         // float4 in n (32)
                float4 v = *(const float4*)(Bm + (long)(k0 + kr) * N + colBlock + nc4 * 4);
                *(float4*)&Bs[kr][nc4 * 4] = v;
            }
        }
        __syncthreads();

        #pragma unroll
        for (int kk = 0; kk < 16; ++kk) {
            float4 a0 = *(const float4*)&As[kk][ty * 8];
            float4 a1 = *(const float4*)&As[kk][ty * 8 + 4];
            float4 b0 = *(const float4*)&Bs[kk][tx * 8];
            float4 b1 = *(const float4*)&Bs[kk][tx * 8 + 4];
            float a[8] = {a0.x, a0.y, a0.z, a0.w, a1.x, a1.y, a1.z, a1.w};
            float b[8] = {b0.x, b0.y, b0.z, b0.w, b1.x, b1.y, b1.z, b1.w};
            #pragma unroll
            for (int i = 0; i < 8; i++)
                #pragma unroll
                for (int j = 0; j < 8; j++)
                    acc[i][j] = fmaf(a[i], b[j], acc[i][j]);
        }
        __syncthreads();
    }

    float bi[8];
    if (BIAS) {
        #pragma unroll
        for (int j = 0; j < 8; j++) bi[j] = bias[colBlock + tx * 8 + j];
    }

    #pragma unroll
    for (int i = 0; i < 8; ++i) {
        int gr = rowBlock + ty * 8 + i;
        if (gr >= M) continue;
        float* crow = C + (long)gr * N + colBlock + tx * 8;
        #pragma unroll
        for (int j4 = 0; j4 < 2; ++j4) {
            float4 r = make_float4(acc[i][j4 * 4 + 0], acc[i][j4 * 4 + 1],
                                   acc[i][j4 * 4 + 2], acc[i][j4 * 4 + 3]);
            if (BIAS) {
                r.x += bi[j4 * 4 + 0]; r.y += bi[j4 * 4 + 1];
                r.z += bi[j4 * 4 + 2]; r.w += bi[j4 * 4 + 3];
            }
            if (ACCUM) {
                float4 c = *(float4*)(crow + j4 * 4);
                r.x += c.x; r.y += c.y; r.z += c.z; r.w += c.w;
            }
            *(float4*)(crow + j4 * 4) = r;
        }
    }
}

// ------------------------- launcher ------------------------------------------
extern "C" void kernel_launch(void* const* d_in, const int* in_sizes, int n_in,
                              void* d_out, int out_size) {
    // metadata order: source, target, enc_attn, source_seq_out, emb,
    //                 affine_w, affine_b, conv_w, conv_b, map_w, map_b
    const int*   target   = (const int*)d_in[1];
    const float* enc_attn = (const float*)d_in[2];
    const float* src_seq  = (const float*)d_in[3];
    const float* emb      = (const float*)d_in[4];
    const float* affine_w = (const float*)d_in[5];
    const float* affine_b = (const float*)d_in[6];
    const float* conv_w   = (const float*)d_in[7];
    const float* conv_b   = (const float*)d_in[8];
    const float* map_w    = (const float*)d_in[9];
    const float* map_b    = (const float*)d_in[10];
    float* out = (float*)d_out;

    float *G, *U, *COL, *Y, *DEC, *SC;
    cudaGetSymbolAddress((void**)&G,   g_G);
    cudaGetSymbolAddress((void**)&U,   g_u);
    cudaGetSymbolAddress((void**)&COL, g_col);
    cudaGetSymbolAddress((void**)&Y,   g_y);
    cudaGetSymbolAddress((void**)&DEC, g_dec);
    cudaGetSymbolAddress((void**)&SC,  g_sc);

    // 1. gather embeddings
    gather_kernel<<<(NM1 * 64 + 255) / 256, 256>>>(target, emb);

    // 2. affine: U = G @ affine_w^T + affine_b   (M=32768, N=512, K=256)
    sgemm128<true, false, true><<<dim3(4, 256, 1), 256>>>(
        G, affine_w, affine_b, U, NM1, NC2, NE, 0, 0, 0);

    // 3. im2col
    im2col_kernel<<<(int)(((long)NM2 * 384 + 255) / 256), 256>>>();

    // 4. conv as GEMM: Y = COL @ conv_w^T + conv_b (M=32736, N=512, K=1536)
    sgemm128<true, false, true><<<dim3(4, 256, 1), 256>>>(
        COL, conv_w, conv_b, Y, NM2, NC2, KCONV, 0, 0, 0);

    // 5. GLU: relu + channel softmax
    glu_kernel<<<NM2, 256>>>();

    // 6. dec2 = DEC @ map_w^T + map_b -> out    (M=32736, N=512, K=256)
    sgemm128<true, false, true><<<dim3(4, 256, 1), 256>>>(
        DEC, map_w, map_b, out, NM2, NC2, NH, 0, 0, 0);

    // 7. scores = DEC @ enc_attn^T (batched, M=1023, N=1024, K=256)
    sgemm128<true, false, false><<<dim3(8, 8, NB), 256>>>(
        DEC, enc_attn, nullptr, SC, NL, NS, NH,
        (long)NL * NH, (long)NS * NH, (long)NL * NS);

    // 8. softmax over s
    softmax_rows_kernel<<<NM2, 256>>>();

    // 9. out += attn @ src_seq (batched NN, M=1023, N=512, K=1024)
    sgemm128<false, true, false><<<dim3(4, 8, NB), 256>>>(
        SC, src_seq, nullptr, out, NL, NC2, NS,
        (long)NL * NS, (long)NS * NC2, (long)NL * NC2);
}

// round 3
// speedup vs baseline: 2.0729x; 2.0729x over previous
#include <cuda_runtime.h>
#include <cuda_bf16.h>
#include <cstdint>

#define NB   32
#define NL   1023
#define NS   1024
#define NH   256
#define NC2  512
#define NE   256
#define NM1  32768
#define NM2  32736

// ---------------- scratch ----------------------------------------------------
__device__ __nv_bfloat16 g_Ghi[NM1 * NE],  g_Glo[NM1 * NE];
__device__ __nv_bfloat16 g_Uhi[NM1 * NC2], g_Ulo[NM1 * NC2];
__device__ float         g_Y  [NM2 * NC2];
__device__ __nv_bfloat16 g_Dhi[NM2 * NH],  g_Dlo[NM2 * NH];
__device__ float         g_SC [(long)NM2 * NS];
__device__ __nv_bfloat16 g_AThi[(long)NM2 * NS], g_ATlo[(long)NM2 * NS];
__device__ __nv_bfloat16 g_AWb[NC2 * 3 * NE];
__device__ __nv_bfloat16 g_CWb[NC2 * 3 * 1536];
__device__ __nv_bfloat16 g_MWb[NC2 * 3 * NH];
__device__ __nv_bfloat16 g_EAb[(long)NB * NS * 3 * NH];
__device__ __nv_bfloat16 g_SST[(long)NB * NC2 * 3 * NS];

// ---------------- helpers ----------------------------------------------------
__device__ __forceinline__ uint32_t smem_u32(const void* p) {
    uint32_t a;
    asm("{ .reg .u64 t; cvta.to.shared.u64 t, %1; cvt.u32.u64 %0, t; }" : "=r"(a) : "l"(p));
    return a;
}
__device__ __forceinline__ void cpasync16(uint32_t s, const void* g, bool pred) {
    int sz = pred ? 16 : 0;
    asm volatile("cp.async.cg.shared.global [%0], [%1], 16, %2;\n" :: "r"(s), "l"(g), "r"(sz));
}
__device__ __forceinline__ void cp_commit() { asm volatile("cp.async.commit_group;\n" ::: "memory"); }

__device__ __forceinline__ void ldm4(uint32_t* r, uint32_t a) {
    asm volatile("ldmatrix.sync.aligned.m8n8.x4.shared.b16 {%0,%1,%2,%3}, [%4];"
                 : "=r"(r[0]), "=r"(r[1]), "=r"(r[2]), "=r"(r[3]) : "r"(a));
}
__device__ __forceinline__ void mma16816(float* c, const uint32_t* a, const uint32_t* b) {
    asm volatile(
        "mma.sync.aligned.m16n8k16.row.col.f32.bf16.bf16.f32 "
        "{%0,%1,%2,%3}, {%4,%5,%6,%7}, {%8,%9}, {%0,%1,%2,%3};"
        : "+f"(c[0]), "+f"(c[1]), "+f"(c[2]), "+f"(c[3])
        : "r"(a[0]), "r"(a[1]), "r"(a[2]), "r"(a[3]), "r"(b[0]), "r"(b[1]));
}
__device__ __forceinline__ void split2(float v, __nv_bfloat16& h, __nv_bfloat16& l) {
    h = __float2bfloat16(v);
    l = __float2bfloat16(v - __bfloat162float(h));
}

// ---------------- conversion kernels ----------------------------------------
__global__ void split_bhl(const float* __restrict__ src, __nv_bfloat16* __restrict__ dst,
                          int K, long total) {
    long gid = (long)blockIdx.x * blockDim.x + threadIdx.x;
    if (gid >= total) return;
    long n = gid / K;
    int  k = (int)(gid - n * K);
    float v = src[gid];
    __nv_bfloat16 h, l; split2(v, h, l);
    long b0 = n * 3 * (long)K;
    dst[b0 + k] = h;
    dst[b0 + K + k] = l;
    dst[b0 + 2 * K + k] = h;
}

__global__ void gather_split(const int* __restrict__ target, const float* __restrict__ emb) {
    long gid = (long)blockIdx.x * blockDim.x + threadIdx.x;
    if (gid >= (long)NM1 * NE) return;
    int m = (int)(gid >> 8);
    int k = (int)(gid & 255);
    int b = m >> 10, t = m & 1023;
    int idx = target[t * NB + b];
    float v = emb[(long)idx * NE + k];
    __nv_bfloat16 h, l; split2(v, h, l);
    g_Ghi[gid] = h; g_Glo[gid] = l;
}

// src_seq (b,s,d) f32 -> SST (b, d, [hi(1024)|lo|hi]) bf16
__global__ void sst_kernel(const float* __restrict__ src) {
    __shared__ float tile[32][33];
    int b = blockIdx.z;
    int s0 = blockIdx.x * 32, d0 = blockIdx.y * 32;
    int tx = threadIdx.x, ty = threadIdx.y;
    tile[ty][tx] = src[((long)b * NS + s0 + ty) * NC2 + d0 + tx];
    __syncthreads();
    int d = d0 + ty, s = s0 + tx;
    float v = tile[tx][ty];
    __nv_bfloat16 h, l; split2(v, h, l);
    long base = ((long)b * NC2 + d) * (3 * NS) + s;
    g_SST[base] = h; g_SST[base + NS] = l; g_SST[base + 2 * NS] = h;
}

__global__ void glu_kernel() {
    int m = blockIdx.x;
    int h = threadIdx.x;
    float a = g_Y[(long)m * NC2 + h];
    float g = g_Y[(long)m * NC2 + NH + h];
    a = fmaxf(a, 0.f); g = fmaxf(g, 0.f);
    __shared__ float red[8];
    float v = g;
    #pragma unroll
    for (int o = 16; o > 0; o >>= 1) v = fmaxf(v, __shfl_xor_sync(~0u, v, o));
    if ((h & 31) == 0) red[h >> 5] = v;
    __syncthreads();
    float mx = red[0];
    #pragma unroll
    for (int i = 1; i < 8; i++) mx = fmaxf(mx, red[i]);
    float e = expf(g - mx);
    __syncthreads();
    v = e;
    #pragma unroll
    for (int o = 16; o > 0; o >>= 1) v += __shfl_xor_sync(~0u, v, o);
    if ((h & 31) == 0) red[h >> 5] = v;
    __syncthreads();
    float sum = 0.f;
    #pragma unroll
    for (int i = 0; i < 8; i++) sum += red[i];
    float dec = a * e / sum;
    __nv_bfloat16 hi, lo; split2(dec, hi, lo);
    g_Dhi[(long)m * NH + h] = hi;
    g_Dlo[(long)m * NH + h] = lo;
}

__global__ void softmax_rows_kernel() {
    int m = blockIdx.x;
    int h = threadIdx.x;
    const float* row = g_SC + (long)m * NS;
    float x0 = row[h], x1 = row[h + 256], x2 = row[h + 512], x3 = row[h + 768];
    __shared__ float red[8];
    float v = fmaxf(fmaxf(x0, x1), fmaxf(x2, x3));
    #pragma unroll
    for (int o = 16; o > 0; o >>= 1) v = fmaxf(v, __shfl_xor_sync(~0u, v, o));
    if ((h & 31) == 0) red[h >> 5] = v;
    __syncthreads();
    float mx = red[0];
    #pragma unroll
    for (int i = 1; i < 8; i++) mx = fmaxf(mx, red[i]);
    float e0 = expf(x0 - mx), e1 = expf(x1 - mx), e2 = expf(x2 - mx), e3 = expf(x3 - mx);
    __syncthreads();
    v = e0 + e1 + e2 + e3;
    #pragma unroll
    for (int o = 16; o > 0; o >>= 1) v += __shfl_xor_sync(~0u, v, o);
    if ((h & 31) == 0) red[h >> 5] = v;
    __syncthreads();
    float sum = 0.f;
    #pragma unroll
    for (int i = 0; i < 8; i++) sum += red[i];
    float inv = 1.f / sum;
    long base = (long)m * NS;
    #pragma unroll
    for (int q = 0; q < 4; q++) {
        float e = (q == 0 ? e0 : q == 1 ? e1 : q == 2 ? e2 : e3) * inv;
        __nv_bfloat16 hi, lo; split2(e, hi, lo);
        g_AThi[base + h + q * 256] = hi;
        g_ATlo[base + h + q * 256] = lo;
    }
}

// ---------------- mma.sync bf16 GEMM -----------------------------------------
// C[M, N] = A'[M, 3K] * B'[N, 3K]^T ; A' logical [Ahi | Ahi | Alo], B' = [hi|lo|hi].
// 128x128 tile, BK=32, 4-stage cp.async, 256 thr (8 warps, 2x4 -> 64x32 warp tile).
// AMODE 0: rows (z*Mb + l) * K.  AMODE 1 (conv): Uhi/Ulo (b,1024,512), t=l-2+tap.
// EPI: 0 f32+bias, 1 f32, 2 f32 accumulate, 3 split(hi/lo bf16, ld 512)+bias.
#define GEMM_SMEM (4 * 16384)

template <int AMODE, int EPI>
__global__ __launch_bounds__(256, 2)
void gemm_mma(const __nv_bfloat16* __restrict__ Ahi, const __nv_bfloat16* __restrict__ Alo,
              int KB, const __nv_bfloat16* __restrict__ Bm, long bBatch,
              const float* __restrict__ bias,
              float* __restrict__ C, int cLd,
              __nv_bfloat16* __restrict__ Ohi, __nv_bfloat16* __restrict__ Olo,
              int Mb) {
    extern __shared__ char smem[];
    const uint32_t sb = smem_u32(smem);
    const int tid = threadIdx.x;
    const int z  = blockIdx.z;
    const int l0 = blockIdx.y * 128;
    const int n0 = blockIdx.x * 128;
    const int Kp = 3 * KB;
    const int NK = Kp / 32;
    const __nv_bfloat16* Bb = Bm + (long)z * bBatch;

    auto load_tile = [&](int kt, int st) {
        const int k0 = kt * 32;
        const int seg = k0 / KB;
        const int rem0 = k0 - seg * KB;
        const __nv_bfloat16* Ab = (seg < 2) ? Ahi : Alo;
        const uint32_t sA = sb + st * 16384;
        const uint32_t sB = sA + 8192;
        #pragma unroll
        for (int i = 0; i < 2; i++) {
            int c = tid + i * 256;          // 0..511
            int m = c >> 2, kc = c & 3;
            int l = l0 + m;
            long g; bool ok;
            if (AMODE == 0) {
                ok = (l < Mb);
                g = ((long)z * Mb + l) * (long)KB + rem0 + kc * 8;
            } else {
                int tap = rem0 >> 9;
                int ch = (rem0 & 511) + kc * 8;
                int t = l - 2 + tap;
                ok = (l < Mb) && (t >= 0);
                g = ((long)z * 1024 + t) * 512 + ch;
            }
            cpasync16(sA + m * 64 + ((uint32_t)(kc ^ (m & 3)) << 4), Ab + (ok ? g : 0), ok);
        }
        #pragma unroll
        for (int i = 0; i < 2; i++) {
            int c = tid + i * 256;
            int n = c >> 2, kc = c & 3;
            cpasync16(sB + n * 64 + ((uint32_t)(kc ^ (n & 3)) << 4),
                      Bb + (long)(n0 + n) * Kp + k0 + kc * 8, true);
        }
        cp_commit();
    };

    float acc[4][4][4];
    #pragma unroll
    for (int i = 0; i < 4; i++)
        #pragma unroll
        for (int j = 0; j < 4; j++)
            #pragma unroll
            for (int q = 0; q < 4; q++) acc[i][j][q] = 0.f;

    const int w = tid >> 5, lid = tid & 31;
    const int wm = w >> 2, wn = w & 3;          // warp grid 2 x 4
    const int rl = wm * 64 + (lid & 15);        // A ldmatrix row
    const int aC = lid >> 4;                    // A k-chunk bit
    const int nl = wn * 32 + ((lid >> 4) << 3) + (lid & 7);  // B ldmatrix row
    const int bC = (lid >> 3) & 1;              // B k-chunk bit

    load_tile(0, 0); load_tile(1, 1); load_tile(2, 2);

    for (int kt = 0; kt < NK; kt++) {
        const int st = kt & 3;
        asm volatile("cp.async.wait_group 2;\n" ::: "memory");
        __syncthreads();
        if (kt + 3 < NK) load_tile(kt + 3, (kt + 3) & 3);
        else cp_commit();

        const uint32_t sA = sb + st * 16384;
        const uint32_t sB = sA + 8192;
        #pragma unroll
        for (int ks = 0; ks < 2; ks++) {
            uint32_t a[4][4];
            #pragma unroll
            for (int i = 0; i < 4; i++) {
                int r = rl + i * 16;
                ldm4(a[i], sA + r * 64 + ((uint32_t)((ks * 2 + aC) ^ (r & 3)) << 4));
            }
            uint32_t b[4][2];
            #pragma unroll
            for (int jj = 0; jj < 2; jj++) {
                int n = nl + jj * 16;
                uint32_t t[4];
                ldm4(t, sB + n * 64 + ((uint32_t)((ks * 2 + bC) ^ (n & 3)) << 4));
                b[jj * 2][0] = t[0]; b[jj * 2][1] = t[1];
                b[jj * 2 + 1][0] = t[2]; b[jj * 2 + 1][1] = t[3];
            }
            #pragma unroll
            for (int i = 0; i < 4; i++)
                #pragma unroll
                for (int j = 0; j < 4; j++)
                    mma16816(acc[i][j], a[i], b[j]);
        }
    }

    // ---------------- epilogue (registers -> global) ----------------
    const int g  = lid >> 2, t4 = lid & 3;
    #pragma unroll
    for (int i = 0; i < 4; i++) {
        #pragma unroll
        for (int h = 0; h < 2; h++) {
            int row = l0 + wm * 64 + i * 16 + g + h * 8;
            if (row >= Mb) continue;
            long grow = (long)z * Mb + row;
            #pragma unroll
            for (int j = 0; j < 4; j++) {
                int col = n0 + wn * 32 + j * 8 + 2 * t4;
                float v0 = acc[i][j][h * 2 + 0];
                float v1 = acc[i][j][h * 2 + 1];
                if (EPI == 0 || EPI == 3) { v0 += bias[col]; v1 += bias[col + 1]; }
                if (EPI == 3) {
                    __nv_bfloat16 h0, l0b, h1, l1b;
                    split2(v0, h0, l0b); split2(v1, h1, l1b);
                    __nv_bfloat162 hh; hh.x = h0; hh.y = h1;
                    __nv_bfloat162 ll; ll.x = l0b; ll.y = l1b;
                    *(__nv_bfloat162*)(Ohi + grow * 512 + col) = hh;
                    *(__nv_bfloat162*)(Olo + grow * 512 + col) = ll;
                } else {
                    float* cp = C + grow * (long)cLd + col;
                    if (EPI == 2) { v0 += cp[0]; v1 += cp[1]; }
                    float2 r; r.x = v0; r.y = v1;
                    *(float2*)cp = r;
                }
            }
        }
    }
}

// ---------------- launcher ---------------------------------------------------
extern "C" void kernel_launch(void* const* d_in, const int* in_sizes, int n_in,
                              void* d_out, int out_size) {
    const int*   target   = (const int*)d_in[1];
    const float* enc_attn = (const float*)d_in[2];
    const float* src_seq  = (const float*)d_in[3];
    const float* emb      = (const float*)d_in[4];
    const float* affine_b = (const float*)d_in[6];
    const float* conv_b   = (const float*)d_in[8];
    const float* map_b    = (const float*)d_in[10];
    const float* affine_w = (const float*)d_in[5];
    const float* conv_w   = (const float*)d_in[7];
    const float* map_w    = (const float*)d_in[9];
    float* out = (float*)d_out;

    __nv_bfloat16 *Ghi, *Glo, *Uhi, *Ulo, *Dhi, *Dlo, *AThi, *ATlo, *AWb, *CWb, *MWb, *EAb, *SST;
    float *Y, *SC;
    cudaGetSymbolAddress((void**)&Ghi, g_Ghi);   cudaGetSymbolAddress((void**)&Glo, g_Glo);
    cudaGetSymbolAddress((void**)&Uhi, g_Uhi);   cudaGetSymbolAddress((void**)&Ulo, g_Ulo);
    cudaGetSymbolAddress((void**)&Y,   g_Y);
    cudaGetSymbolAddress((void**)&Dhi, g_Dhi);   cudaGetSymbolAddress((void**)&Dlo, g_Dlo);
    cudaGetSymbolAddress((void**)&SC,  g_SC);
    cudaGetSymbolAddress((void**)&AThi, g_AThi); cudaGetSymbolAddress((void**)&ATlo, g_ATlo);
    cudaGetSymbolAddress((void**)&AWb, g_AWb);   cudaGetSymbolAddress((void**)&CWb, g_CWb);
    cudaGetSymbolAddress((void**)&MWb, g_MWb);   cudaGetSymbolAddress((void**)&EAb, g_EAb);
    cudaGetSymbolAddress((void**)&SST, g_SST);

    cudaFuncSetAttribute(gemm_mma<0, 3>, cudaFuncAttributeMaxDynamicSharedMemorySize, GEMM_SMEM);
    cudaFuncSetAttribute(gemm_mma<1, 0>, cudaFuncAttributeMaxDynamicSharedMemorySize, GEMM_SMEM);
    cudaFuncSetAttribute(gemm_mma<0, 0>, cudaFuncAttributeMaxDynamicSharedMemorySize, GEMM_SMEM);
    cudaFuncSetAttribute(gemm_mma<0, 1>, cudaFuncAttributeMaxDynamicSharedMemorySize, GEMM_SMEM);
    cudaFuncSetAttribute(gemm_mma<0, 2>, cudaFuncAttributeMaxDynamicSharedMemorySize, GEMM_SMEM);

    // conversions
    split_bhl<<<(512 * 256 + 255) / 256, 256>>>(affine_w, AWb, 256, 512 * 256);
    split_bhl<<<(512 * 1536 + 255) / 256, 256>>>(conv_w, CWb, 1536, 512 * 1536);
    split_bhl<<<(512 * 256 + 255) / 256, 256>>>(map_w, MWb, 256, 512 * 256);
    split_bhl<<<(int)(((long)NM1 * 256 + 255) / 256), 256>>>(enc_attn, EAb, 256, (long)NM1 * 256);
    sst_kernel<<<dim3(NS / 32, NC2 / 32, NB), dim3(32, 32)>>>(src_seq);
    gather_split<<<(int)(((long)NM1 * NE + 255) / 256), 256>>>(target, emb);

    // 1. affine: U(split) = G @ AW^T + b      M=32*1024, N=512, K'=768
    gemm_mma<0, 3><<<dim3(4, 8, NB), 256, GEMM_SMEM>>>(
        Ghi, Glo, 256, AWb, 0, affine_b, nullptr, 0, Uhi, Ulo, 1024);
    // 2. conv: Y = im2col(U) @ CW^T + b       M=32*1023, N=512, K'=4608
    gemm_mma<1, 0><<<dim3(4, 8, NB), 256, GEMM_SMEM>>>(
        Uhi, Ulo, 1536, CWb, 0, conv_b, Y, 512, nullptr, nullptr, NL);
    // 3. GLU
    glu_kernel<<<NM2, 256>>>();
    // 4. map: out = dec @ MW^T + b            M=32*1023, N=512, K'=768
    gemm_mma<0, 0><<<dim3(4, 8, NB), 256, GEMM_SMEM>>>(
        Dhi, Dlo, 256, MWb, 0, map_b, out, 512, nullptr, nullptr, NL);
    // 5. scores = dec @ enc^T (batched)       N=1024, K'=768
    gemm_mma<0, 1><<<dim3(8, 8, NB), 256, GEMM_SMEM>>>(
        Dhi, Dlo, 256, EAb, (long)NS * 768, nullptr, SC, NS, nullptr, nullptr, NL);
    // 6. softmax -> split attn
    softmax_rows_kernel<<<NM2, 256>>>();
    // 7. out += attn @ src_seq (batched)      N=512, K'=3072
    gemm_mma<0, 2><<<dim3(4, 8, NB), 256, GEMM_SMEM>>>(
        AThi, ATlo, 1024, SST, (long)NC2 * 3 * NS, nullptr, out, 512, nullptr, nullptr, NL);
}

// round 4
// speedup vs baseline: 2.5319x; 1.2214x over previous
#include <cuda_runtime.h>
#include <cuda_bf16.h>
#include <cstdint>

#define NB   32
#define NL   1023
#define NS   1024
#define NH   256
#define NC2  512
#define NE   256
#define NM1  32768
#define NM2  32736

// ---------------- scratch ----------------------------------------------------
__device__ __nv_bfloat16 g_Ghi[NM1 * NE],  g_Glo[NM1 * NE];
__device__ float         g_Y  [NM2 * NC2];
__device__ __nv_bfloat16 g_Dhi[NM2 * NH],  g_Dlo[NM2 * NH];
__device__ float         g_SC [(long)NM2 * NS];
__device__ __nv_bfloat16 g_AThi[(long)NM2 * NS], g_ATlo[(long)NM2 * NS];
__device__ __nv_bfloat16 g_CWh[NC2 * 1536], g_CWl[NC2 * 1536];  // conv_w split flat
__device__ __nv_bfloat16 g_AWT[NE * 3 * NC2];                   // affine_w^T [h|l|h]
__device__ __nv_bfloat16 g_FWB[NC2 * 3 * 768];                  // fused weight [h|l|h]
__device__ __nv_bfloat16 g_MWb[NC2 * 3 * NH];
__device__ __nv_bfloat16 g_EAb[(long)NB * NS * 3 * NH];
__device__ __nv_bfloat16 g_SST[(long)NB * NC2 * 3 * NS];
__device__ float         g_BC [3 * NC2];       // per-tap bias contribution
__device__ float         g_BR [3 * NC2];       // 3 bias rows (by min(l,2))

// ---------------- helpers ----------------------------------------------------
__device__ __forceinline__ uint32_t smem_u32(const void* p) {
    uint32_t a;
    asm("{ .reg .u64 t; cvta.to.shared.u64 t, %1; cvt.u32.u64 %0, t; }" : "=r"(a) : "l"(p));
    return a;
}
__device__ __forceinline__ void cpasync16(uint32_t s, const void* g, bool pred) {
    int sz = pred ? 16 : 0;
    asm volatile("cp.async.cg.shared.global [%0], [%1], 16, %2;\n" :: "r"(s), "l"(g), "r"(sz));
}
__device__ __forceinline__ void cp_commit() { asm volatile("cp.async.commit_group;\n" ::: "memory"); }

__device__ __forceinline__ void ldm4(uint32_t* r, uint32_t a) {
    asm volatile("ldmatrix.sync.aligned.m8n8.x4.shared.b16 {%0,%1,%2,%3}, [%4];"
                 : "=r"(r[0]), "=r"(r[1]), "=r"(r[2]), "=r"(r[3]) : "r"(a));
}
__device__ __forceinline__ void mma16816(float* c, const uint32_t* a, const uint32_t* b) {
    asm volatile(
        "mma.sync.aligned.m16n8k16.row.col.f32.bf16.bf16.f32 "
        "{%0,%1,%2,%3}, {%4,%5,%6,%7}, {%8,%9}, {%0,%1,%2,%3};"
        : "+f"(c[0]), "+f"(c[1]), "+f"(c[2]), "+f"(c[3])
        : "r"(a[0]), "r"(a[1]), "r"(a[2]), "r"(a[3]), "r"(b[0]), "r"(b[1]));
}
__device__ __forceinline__ void split2(float v, __nv_bfloat16& h, __nv_bfloat16& l) {
    h = __float2bfloat16(v);
    l = __float2bfloat16(v - __bfloat162float(h));
}

// ---------------- conversion kernels ----------------------------------------
// dst[n, 3K] = [hi | lo | hi] from src[n, K]
__global__ void split_bhl(const float* __restrict__ src, __nv_bfloat16* __restrict__ dst,
                          int K, long total) {
    long gid = (long)blockIdx.x * blockDim.x + threadIdx.x;
    if (gid >= total) return;
    long n = gid / K;
    int  k = (int)(gid - n * K);
    float v = src[gid];
    __nv_bfloat16 h, l; split2(v, h, l);
    long b0 = n * 3 * (long)K;
    dst[b0 + k] = h;
    dst[b0 + K + k] = l;
    dst[b0 + 2 * K + k] = h;
}

// elementwise split of conv_w into two flat bf16 arrays
__global__ void split_flat(const float* __restrict__ src, long total) {
    long gid = (long)blockIdx.x * blockDim.x + threadIdx.x;
    if (gid >= total) return;
    __nv_bfloat16 h, l; split2(src[gid], h, l);
    g_CWh[gid] = h; g_CWl[gid] = l;
}

// affine_w [512(i), 256(e)] -> AWT[e, [hi(i 512) | lo | hi]]
__global__ void awt_kernel(const float* __restrict__ aw) {
    __shared__ float tile[32][33];
    int i0 = blockIdx.x * 32, e0 = blockIdx.y * 32;
    int tx = threadIdx.x, ty = threadIdx.y;
    tile[ty][tx] = aw[(i0 + ty) * NE + e0 + tx];
    __syncthreads();
    float v = tile[tx][ty];          // = aw[i0+tx][e0+ty]
    __nv_bfloat16 h, l; split2(v, h, l);
    long base = (long)(e0 + ty) * 1536 + i0 + tx;
    g_AWT[base] = h; g_AWT[base + 512] = l; g_AWT[base + 1024] = h;
}

// bconst[tap, o] = sum_i conv_w[o,tap,i] * affine_b[i]   (warp per (tap,o))
__global__ void bconst_kernel(const float* __restrict__ cw, const float* __restrict__ ab) {
    int wid = (blockIdx.x * blockDim.x + threadIdx.x) >> 5;
    int lane = threadIdx.x & 31;
    if (wid >= 1536) return;
    int tap = wid / 512, o = wid % 512;
    const float* row = cw + (long)o * 1536 + tap * 512;
    float s = 0.f;
    for (int i = lane; i < 512; i += 32) s += row[i] * ab[i];
    #pragma unroll
    for (int off = 16; off > 0; off >>= 1) s += __shfl_xor_sync(~0u, s, off);
    if (lane == 0) g_BC[tap * 512 + o] = s;
}

// bias rows: BR[j][o] = conv_b[o] + sum_{tap >= 2-j} BC[tap][o], j = min(l,2)
__global__ void biasrows_kernel(const float* __restrict__ conv_b) {
    int o = blockIdx.x * blockDim.x + threadIdx.x;
    if (o >= 512) return;
    float b = conv_b[o];
    float c0 = g_BC[o], c1 = g_BC[512 + o], c2 = g_BC[1024 + o];
    g_BR[o]        = b + c2;
    g_BR[512 + o]  = b + c1 + c2;
    g_BR[1024 + o] = b + c0 + c1 + c2;
}

// gather emb[target] -> Ghi/Glo (rows m = b*1024 + t, K=256)
__global__ void gather_split(const int* __restrict__ target, const float* __restrict__ emb) {
    long gid = (long)blockIdx.x * blockDim.x + threadIdx.x;
    if (gid >= (long)NM1 * NE) return;
    int m = (int)(gid >> 8);
    int k = (int)(gid & 255);
    int b = m >> 10, t = m & 1023;
    int idx = target[t * NB + b];
    float v = emb[(long)idx * NE + k];
    __nv_bfloat16 h, l; split2(v, h, l);
    g_Ghi[gid] = h; g_Glo[gid] = l;
}

// src_seq (b,s,d) f32 -> SST (b, d, [hi(1024)|lo|hi]) bf16
__global__ void sst_kernel(const float* __restrict__ src) {
    __shared__ float tile[32][33];
    int b = blockIdx.z;
    int s0 = blockIdx.x * 32, d0 = blockIdx.y * 32;
    int tx = threadIdx.x, ty = threadIdx.y;
    tile[ty][tx] = src[((long)b * NS + s0 + ty) * NC2 + d0 + tx];
    __syncthreads();
    int d = d0 + ty, s = s0 + tx;
    float v = tile[tx][ty];
    __nv_bfloat16 h, l; split2(v, h, l);
    long base = ((long)b * NC2 + d) * (3 * NS) + s;
    g_SST[base] = h; g_SST[base + NS] = l; g_SST[base + 2 * NS] = h;
}

__global__ void glu_kernel() {
    int m = blockIdx.x;
    int h = threadIdx.x;
    float a = g_Y[(long)m * NC2 + h];
    float g = g_Y[(long)m * NC2 + NH + h];
    a = fmaxf(a, 0.f); g = fmaxf(g, 0.f);
    __shared__ float red[8];
    float v = g;
    #pragma unroll
    for (int o = 16; o > 0; o >>= 1) v = fmaxf(v, __shfl_xor_sync(~0u, v, o));
    if ((h & 31) == 0) red[h >> 5] = v;
    __syncthreads();
    float mx = red[0];
    #pragma unroll
    for (int i = 1; i < 8; i++) mx = fmaxf(mx, red[i]);
    float e = expf(g - mx);
    __syncthreads();
    v = e;
    #pragma unroll
    for (int o = 16; o > 0; o >>= 1) v += __shfl_xor_sync(~0u, v, o);
    if ((h & 31) == 0) red[h >> 5] = v;
    __syncthreads();
    float sum = 0.f;
    #pragma unroll
    for (int i = 0; i < 8; i++) sum += red[i];
    float dec = a * e / sum;
    __nv_bfloat16 hi, lo; split2(dec, hi, lo);
    g_Dhi[(long)m * NH + h] = hi;
    g_Dlo[(long)m * NH + h] = lo;
}

__global__ void softmax_rows_kernel() {
    int m = blockIdx.x;
    int h = threadIdx.x;
    const float* row = g_SC + (long)m * NS;
    float x0 = row[h], x1 = row[h + 256], x2 = row[h + 512], x3 = row[h + 768];
    __shared__ float red[8];
    float v = fmaxf(fmaxf(x0, x1), fmaxf(x2, x3));
    #pragma unroll
    for (int o = 16; o > 0; o >>= 1) v = fmaxf(v, __shfl_xor_sync(~0u, v, o));
    if ((h & 31) == 0) red[h >> 5] = v;
    __syncthreads();
    float mx = red[0];
    #pragma unroll
    for (int i = 1; i < 8; i++) mx = fmaxf(mx, red[i]);
    float e0 = expf(x0 - mx), e1 = expf(x1 - mx), e2 = expf(x2 - mx), e3 = expf(x3 - mx);
    __syncthreads();
    v = e0 + e1 + e2 + e3;
    #pragma unroll
    for (int o = 16; o > 0; o >>= 1) v += __shfl_xor_sync(~0u, v, o);
    if ((h & 31) == 0) red[h >> 5] = v;
    __syncthreads();
    float sum = 0.f;
    #pragma unroll
    for (int i = 0; i < 8; i++) sum += red[i];
    float inv = 1.f / sum;
    long base = (long)m * NS;
    #pragma unroll
    for (int q = 0; q < 4; q++) {
        float e = (q == 0 ? e0 : q == 1 ? e1 : q == 2 ? e2 : e3) * inv;
        __nv_bfloat16 hi, lo; split2(e, hi, lo);
        g_AThi[base + h + q * 256] = hi;
        g_ATlo[base + h + q * 256] = lo;
    }
}

// ---------------- mma.sync bf16 GEMM -----------------------------------------
// C[M, N] = A'[M, 3K] * B'[N, 3K]^T ; A' logical [Ahi | Ahi | Alo], B' = [hi|lo|hi].
// 128x128 tile, BK=32, 4-stage cp.async, 256 thr (8 warps, 2x4 -> 64x32 warp tile).
// AMODE 0: rows (z*Mb + l) * lda + k.  AMODE 2 (fused conv on G): k -> (tap, e),
//          t = l-2+tap, read (z*1024+t)*256 + e; zero-fill t<0.
// EPI: 0 f32+bias1D, 1 f32, 2 f32 accumulate,
//      3 FW split write ([h|l|h] at +0/+768/+1536, ld 2304, no bias),
//      5 f32 + bias2D rows BR[min(l,2)].
#define GEMM_SMEM (4 * 16384)

template <int AMODE, int EPI>
__global__ __launch_bounds__(256, 2)
void gemm_mma(const __nv_bfloat16* __restrict__ Ahi, const __nv_bfloat16* __restrict__ Alo,
              int KB, int lda, const __nv_bfloat16* __restrict__ Bm, long bBatch,
              const float* __restrict__ bias,
              float* __restrict__ C, int cLd,
              __nv_bfloat16* __restrict__ Ohi,
              int Mb) {
    extern __shared__ char smem[];
    const uint32_t sb = smem_u32(smem);
    const int tid = threadIdx.x;
    const int z  = blockIdx.z;
    const int l0 = blockIdx.y * 128;
    const int n0 = blockIdx.x * 128;
    const int Kp = 3 * KB;
    const int NK = Kp / 32;
    const __nv_bfloat16* Bb = Bm + (long)z * bBatch;

    auto load_tile = [&](int kt, int st) {
        const int k0 = kt * 32;
        const int seg = k0 / KB;
        const int rem0 = k0 - seg * KB;
        const __nv_bfloat16* Ab = (seg < 2) ? Ahi : Alo;
        const uint32_t sA = sb + st * 16384;
        const uint32_t sB = sA + 8192;
        #pragma unroll
        for (int i = 0; i < 2; i++) {
            int c = tid + i * 256;          // 0..511
            int m = c >> 2, kc = c & 3;
            int l = l0 + m;
            long g; bool ok;
            if (AMODE == 0) {
                ok = (l < Mb);
                g = ((long)z * Mb + l) * (long)lda + rem0 + kc * 8;
            } else {                         // fused conv on G
                int tap = rem0 >> 8;
                int e = (rem0 & 255) + kc * 8;
                int t = l - 2 + tap;
                ok = (l < Mb) && (t >= 0);
                g = ((long)z * 1024 + t) * 256 + e;
            }
            cpasync16(sA + m * 64 + ((uint32_t)(kc ^ (m & 3)) << 4), Ab + (ok ? g : 0), ok);
        }
        #pragma unroll
        for (int i = 0; i < 2; i++) {
            int c = tid + i * 256;
            int n = c >> 2, kc = c & 3;
            cpasync16(sB + n * 64 + ((uint32_t)(kc ^ (n & 3)) << 4),
                      Bb + (long)(n0 + n) * Kp + k0 + kc * 8, true);
        }
        cp_commit();
    };

    float acc[4][4][4];
    #pragma unroll
    for (int i = 0; i < 4; i++)
        #pragma unroll
        for (int j = 0; j < 4; j++)
            #pragma unroll
            for (int q = 0; q < 4; q++) acc[i][j][q] = 0.f;

    const int w = tid >> 5, lid = tid & 31;
    const int wm = w >> 2, wn = w & 3;          // warp grid 2 x 4
    const int rl = wm * 64 + (lid & 15);        // A ldmatrix row
    const int aC = lid >> 4;                    // A k-chunk bit
    const int nl = wn * 32 + ((lid >> 4) << 3) + (lid & 7);  // B ldmatrix row
    const int bC = (lid >> 3) & 1;              // B k-chunk bit

    load_tile(0, 0); load_tile(1, 1); load_tile(2, 2);

    for (int kt = 0; kt < NK; kt++) {
        const int st = kt & 3;
        asm volatile("cp.async.wait_group 2;\n" ::: "memory");
        __syncthreads();
        if (kt + 3 < NK) load_tile(kt + 3, (kt + 3) & 3);
        else cp_commit();

        const uint32_t sA = sb + st * 16384;
        const uint32_t sB = sA + 8192;
        #pragma unroll
        for (int ks = 0; ks < 2; ks++) {
            uint32_t a[4][4];
            #pragma unroll
            for (int i = 0; i < 4; i++) {
                int r = rl + i * 16;
                ldm4(a[i], sA + r * 64 + ((uint32_t)((ks * 2 + aC) ^ (r & 3)) << 4));
            }
            uint32_t b[4][2];
            #pragma unroll
            for (int jj = 0; jj < 2; jj++) {
                int n = nl + jj * 16;
                uint32_t t[4];
                ldm4(t, sB + n * 64 + ((uint32_t)((ks * 2 + bC) ^ (n & 3)) << 4));
                b[jj * 2][0] = t[0]; b[jj * 2][1] = t[1];
                b[jj * 2 + 1][0] = t[2]; b[jj * 2 + 1][1] = t[3];
            }
            #pragma unroll
            for (int i = 0; i < 4; i++)
                #pragma unroll
                for (int j = 0; j < 4; j++)
                    mma16816(acc[i][j], a[i], b[j]);
        }
    }

    // ---------------- epilogue ----------------
    const int g  = lid >> 2, t4 = lid & 3;
    #pragma unroll
    for (int i = 0; i < 4; i++) {
        #pragma unroll
        for (int h = 0; h < 2; h++) {
            int row = l0 + wm * 64 + i * 16 + g + h * 8;
            if (row >= Mb) continue;
            long grow = (long)z * Mb + row;
            #pragma unroll
            for (int j = 0; j < 4; j++) {
                int col = n0 + wn * 32 + j * 8 + 2 * t4;
                float v0 = acc[i][j][h * 2 + 0];
                float v1 = acc[i][j][h * 2 + 1];
                if (EPI == 0) { v0 += bias[col]; v1 += bias[col + 1]; }
                if (EPI == 5) {
                    int jb = (row < 2) ? row : 2;
                    v0 += bias[jb * 512 + col]; v1 += bias[jb * 512 + col + 1];
                }
                if (EPI == 3) {
                    __nv_bfloat16 h0, lb0, h1, lb1;
                    split2(v0, h0, lb0); split2(v1, h1, lb1);
                    __nv_bfloat162 hh; hh.x = h0; hh.y = h1;
                    __nv_bfloat162 ll; ll.x = lb0; ll.y = lb1;
                    long base = grow * 2304 + col;
                    *(__nv_bfloat162*)(Ohi + base)        = hh;
                    *(__nv_bfloat162*)(Ohi + base + 768)  = ll;
                    *(__nv_bfloat162*)(Ohi + base + 1536) = hh;
                } else {
                    float* cp = C + grow * (long)cLd + col;
                    if (EPI == 2) { v0 += cp[0]; v1 += cp[1]; }
                    float2 r; r.x = v0; r.y = v1;
                    *(float2*)cp = r;
                }
            }
        }
    }
}

// ---------------- launcher ---------------------------------------------------
extern "C" void kernel_launch(void* const* d_in, const int* in_sizes, int n_in,
                              void* d_out, int out_size) {
    const int*   target   = (const int*)d_in[1];
    const float* enc_attn = (const float*)d_in[2];
    const float* src_seq  = (const float*)d_in[3];
    const float* emb      = (const float*)d_in[4];
    const float* affine_w = (const float*)d_in[5];
    const float* affine_b = (const float*)d_in[6];
    const float* conv_w   = (const float*)d_in[7];
    const float* conv_b   = (const float*)d_in[8];
    const float* map_w    = (const float*)d_in[9];
    const float* map_b    = (const float*)d_in[10];
    float* out = (float*)d_out;

    __nv_bfloat16 *Ghi, *Glo, *Dhi, *Dlo, *AThi, *ATlo, *CWh, *CWl, *AWT, *FWB, *MWb, *EAb, *SST;
    float *Y, *SC, *BR;
    cudaGetSymbolAddress((void**)&Ghi, g_Ghi);   cudaGetSymbolAddress((void**)&Glo, g_Glo);
    cudaGetSymbolAddress((void**)&Y,   g_Y);
    cudaGetSymbolAddress((void**)&Dhi, g_Dhi);   cudaGetSymbolAddress((void**)&Dlo, g_Dlo);
    cudaGetSymbolAddress((void**)&SC,  g_SC);
    cudaGetSymbolAddress((void**)&AThi, g_AThi); cudaGetSymbolAddress((void**)&ATlo, g_ATlo);
    cudaGetSymbolAddress((void**)&CWh, g_CWh);   cudaGetSymbolAddress((void**)&CWl, g_CWl);
    cudaGetSymbolAddress((void**)&AWT, g_AWT);   cudaGetSymbolAddress((void**)&FWB, g_FWB);
    cudaGetSymbolAddress((void**)&MWb, g_MWb);   cudaGetSymbolAddress((void**)&EAb, g_EAb);
    cudaGetSymbolAddress((void**)&SST, g_SST);   cudaGetSymbolAddress((void**)&BR,  g_BR);

    cudaFuncSetAttribute(gemm_mma<0, 3>, cudaFuncAttributeMaxDynamicSharedMemorySize, GEMM_SMEM);
    cudaFuncSetAttribute(gemm_mma<2, 5>, cudaFuncAttributeMaxDynamicSharedMemorySize, GEMM_SMEM);
    cudaFuncSetAttribute(gemm_mma<0, 0>, cudaFuncAttributeMaxDynamicSharedMemorySize, GEMM_SMEM);
    cudaFuncSetAttribute(gemm_mma<0, 1>, cudaFuncAttributeMaxDynamicSharedMemorySize, GEMM_SMEM);
    cudaFuncSetAttribute(gemm_mma<0, 2>, cudaFuncAttributeMaxDynamicSharedMemorySize, GEMM_SMEM);

    // conversions / weight prep
    split_flat<<<(512 * 1536 + 255) / 256, 256>>>(conv_w, 512 * 1536);
    awt_kernel<<<dim3(16, 8), dim3(32, 32)>>>(affine_w);
    bconst_kernel<<<192, 256>>>(conv_w, affine_b);
    biasrows_kernel<<<2, 256>>>(conv_b);
    split_bhl<<<(512 * 256 + 255) / 256, 256>>>(map_w, MWb, 256, 512 * 256);
    split_bhl<<<(int)(((long)NM1 * 256 + 255) / 256), 256>>>(enc_attn, EAb, 256, (long)NM1 * 256);
    sst_kernel<<<dim3(NS / 32, NC2 / 32, NB), dim3(32, 32)>>>(src_seq);
    gather_split<<<(int)(((long)NM1 * NE + 255) / 256), 256>>>(target, emb);

    // 0. fused weight: FW_tap[o,e] = conv_w[o,tap,:] @ affine_w[:,e]  (M=512,N=256,K'=1536)
    for (int tap = 0; tap < 3; tap++)
        gemm_mma<0, 3><<<dim3(2, 4, 1), 256, GEMM_SMEM>>>(
            CWh + tap * 512, CWl + tap * 512, 512, 1536, AWT, 0,
            nullptr, nullptr, 0, FWB + tap * 256, 512);

    // 1. fused conv on G: Y = im2col_E(G) @ FW^T + biasrows  (M=1023/b, N=512, K'=2304)
    gemm_mma<2, 5><<<dim3(4, 8, NB), 256, GEMM_SMEM>>>(
        Ghi, Glo, 768, 0, FWB, 0, BR, Y, 512, nullptr, NL);
    // 2. GLU
    glu_kernel<<<NM2, 256>>>();
    // 3. map: out = dec @ MW^T + b            (M=1023/b, N=512, K'=768)
    gemm_mma<0, 0><<<dim3(4, 8, NB), 256, GEMM_SMEM>>>(
        Dhi, Dlo, 256, 256, MWb, 0, map_b, out, 512, nullptr, NL);
    // 4. scores = dec @ enc^T (batched)       (N=1024, K'=768)
    gemm_mma<0, 1><<<dim3(8, 8, NB), 256, GEMM_SMEM>>>(
        Dhi, Dlo, 256, 256, EAb, (long)NS * 768, nullptr, SC, NS, nullptr, NL);
    // 5. softmax -> split attn
    softmax_rows_kernel<<<NM2, 256>>>();
    // 6. out += attn @ src_seq (batched)      (N=512, K'=3072)
    gemm_mma<0, 2><<<dim3(4, 8, NB), 256, GEMM_SMEM>>>(
        AThi, ATlo, 1024, 1024, SST, (long)NC2 * 3 * NS, nullptr, out, 512, nullptr, NL);
}